// round 14
// baseline (speedup 1.0000x reference)
#include <cuda_runtime.h>
#include <cuda_fp16.h>
#include <math.h>

#define N_NODES 20000
#define K_NB    32
#define D_DIM   128
#define AHP     68    // fp16 tile row stride (u32), split-block layout
#define GRID    296

// ---------------- scratch (device globals: allocation-free) ----------------
__device__ float g_tsf[(size_t)N_NODES * D_DIM];   // self_feats @ self_weights
__device__ float g_tself[N_NODES];                 // self_vecs . gate_self_w

__device__ __forceinline__ float sigmoid_tanh(float x) {
    float t;
    asm("tanh.approx.f32 %0, %1;" : "=f"(t) : "f"(0.5f * x));
    return fmaf(0.5f, t, 0.5f);
}

// pack two f32 -> f16x2 (hi = first arg, lo = second arg)
__device__ __forceinline__ unsigned packh(float hi, float lo) {
    unsigned r;
    asm("cvt.rn.f16x2.f32 %0, %1, %2;" : "=r"(r) : "f"(hi), "f"(lo));
    return r;
}

// fp16 mma m16n8k16, fp32 accumulate
__device__ __forceinline__ void mma_f16(float& c0, float& c1, float& c2, float& c3,
                                        unsigned a0, unsigned a1, unsigned a2, unsigned a3,
                                        unsigned b0, unsigned b1) {
    asm volatile(
        "mma.sync.aligned.m16n8k16.row.col.f32.f16.f16.f32 "
        "{%0,%1,%2,%3}, {%4,%5,%6,%7}, {%8,%9}, {%0,%1,%2,%3};\n"
        : "+f"(c0), "+f"(c1), "+f"(c2), "+f"(c3)
        : "r"(a0), "r"(a1), "r"(a2), "r"(a3), "r"(b0), "r"(b1));
}

// ---------------- kernel 1: tself[n] = dot(self_vecs[n], gate_self_w) ------
__global__ void k_tself(const float* __restrict__ self_vecs,
                        const float* __restrict__ gws) {
    int gtid = blockIdx.x * blockDim.x + threadIdx.x;
    int node = gtid >> 5;
    int lane = gtid & 31;
    if (node >= N_NODES) return;
    float4 a = ((const float4*)(self_vecs + (size_t)node * D_DIM))[lane];
    float4 b = __ldg(&((const float4*)gws)[lane]);
    float s = a.x * b.x + a.y * b.y + a.z * b.z + a.w * b.w;
    #pragma unroll
    for (int o = 16; o > 0; o >>= 1) s += __shfl_down_sync(0xffffffffu, s, o);
    if (lane == 0) g_tself[node] = s;
}

// ---------------- kernel 2: tsf = self_feats @ self_weights ----------------
#define TSF_NODES 16
__global__ void k_tsf(const float* __restrict__ self_feats,
                      const float* __restrict__ Ws) {
    extern __shared__ float sm[];
    float* Wsh = sm;
    float* sfs = sm + D_DIM * D_DIM;
    int t = threadIdx.x;

    for (int i = t; i < (D_DIM * D_DIM) / 4; i += 256)
        ((float4*)Wsh)[i] = ((const float4*)Ws)[i];

    int nbase = blockIdx.x * TSF_NODES;
    const float4* gsf = (const float4*)(self_feats + (size_t)nbase * D_DIM);
    for (int i = t; i < (TSF_NODES * D_DIM) / 4; i += 256)
        ((float4*)sfs)[i] = gsf[i];
    __syncthreads();

    int e = t & 127;
    int g = t >> 7;
    float acc[8];
    #pragma unroll
    for (int m = 0; m < 8; m++) acc[m] = 0.0f;

    #pragma unroll 4
    for (int d = 0; d < D_DIM; d++) {
        float w = Wsh[d * D_DIM + e];
        #pragma unroll
        for (int m = 0; m < 8; m++)
            acc[m] = fmaf(w, sfs[(g * 8 + m) * D_DIM + d], acc[m]);
    }
    #pragma unroll
    for (int m = 0; m < 8; m++)
        g_tsf[(size_t)(nbase + g * 8 + m) * D_DIM + e] = acc[m];
}

// ---------------- k_main helpers -------------------------------------------

// LDG one node tile slice into registers: thread (kk, sub) owns row kk,
// cols sub*16 .. sub*16+15 (coalesced float4s)
__device__ __forceinline__ void load_tile(int p, const float* __restrict__ link,
                                          const float* __restrict__ neigh,
                                          int kk, int sub,
                                          float4 (&lvr)[4], float4 (&nvr)[4]) {
    size_t gb = (((size_t)p * 32 + kk) << 7) + sub * 16;
    const float4* l4 = (const float4*)(link + gb);
    const float4* n4 = (const float4*)(neigh + gb);
    #pragma unroll
    for (int i = 0; i < 4; i++) {
        lvr[i] = __ldg(l4 + i);
        nvr[i] = __ldg(n4 + i);
    }
}

__device__ __forceinline__ void ts_load(int p, int wn, int lane,
                                        float2 (&ts)[2]) {
    if (lane < 4) {
        #pragma unroll
        for (int ns = 0; ns < 2; ns++)
            ts[ns] = *(const float2*)&g_tsf[(size_t)p * D_DIM +
                                            wn * 16 + ns * 8 + lane * 2];
    }
}

// pack 16 floats (4 float4) -> 8 u32 fp16x2, split-block store:
// first 4 u32 at row*AHP + sub*4, last 4 at row*AHP + 32 + sub*4
__device__ __forceinline__ void store_h(unsigned* dst_row, int sub,
                                        const float4 (&v)[4]) {
    uint4 h0, h1;
    h0.x = packh(v[0].y, v[0].x);
    h0.y = packh(v[0].w, v[0].z);
    h0.z = packh(v[1].y, v[1].x);
    h0.w = packh(v[1].w, v[1].z);
    h1.x = packh(v[2].y, v[2].x);
    h1.y = packh(v[2].w, v[2].z);
    h1.z = packh(v[3].y, v[3].x);
    h1.w = packh(v[3].w, v[3].z);
    *(uint4*)(dst_row + sub * 4) = h0;
    *(uint4*)(dst_row + 32 + sub * 4) = h1;
}

// ---------------- kernel 3: main (register dataflow, 2 CTAs/SM) ------------
// 256 threads = 8 warps, warp grid 1(M) x 8(N). Tile = 1 node (32 rows).
// lv/nv LDG->regs (1-iter prefetch), gate in regs, A & nv tiles stored fp16
// to smem (conflict-free split-block layout), B fragments in 32 registers.
__global__ void __launch_bounds__(256, 2)
k_main(const float* __restrict__ neigh,
       const float* __restrict__ link,
       const float* __restrict__ probs,
       const float* __restrict__ gwn,
       const float* __restrict__ gwl,
       const float* __restrict__ Wl,
       float* __restrict__ out) {
    extern __shared__ float sm[];
    unsigned* ah   = (unsigned*)sm;            // 32*68 u32 (fp16 lv tile)
    unsigned* nvh  = ah + 32 * AHP;            // 32*68 u32 (fp16 nv tile)
    float*    csh  = (float*)(nvh + 32 * AHP); // 32
    float*    gwls = csh + 32;                 // 128
    float*    gwns = gwls + D_DIM;             // 128

    int t = threadIdx.x;
    int warp = t >> 5, lane = t & 31;
    int wn = warp;                 // 8 N-groups of 16 cols
    int lp = lane >> 2;
    int lq = lane & 3;
    int kk = t >> 3, sub = t & 7;  // tile row / 16-col slice
    const int G = GRID;

    if (t < D_DIM) { gwls[t] = gwl[t]; gwns[t] = gwn[t]; }

    // ---- B fragments in registers (loop-invariant, 32 regs)
    // element j of Bf[ks]: kb = ks*16 + 2*lq + 8*(j&1); n = wn*16+(j>>1)*8+lp
    uint4 Bf[8];
    #pragma unroll
    for (int ks = 0; ks < 8; ks++) {
        unsigned v[4];
        #pragma unroll
        for (int j = 0; j < 4; j++) {
            int kb = ks * 16 + 2 * lq + 8 * (j & 1);
            int n  = wn * 16 + (j >> 1) * 8 + lp;
            v[j] = packh(__ldg(&Wl[(kb + 1) * D_DIM + n]),
                         __ldg(&Wl[kb * D_DIM + n]));
        }
        Bf[ks] = make_uint4(v[0], v[1], v[2], v[3]);
    }

    // ---- prologue: tile p0 into registers
    int p0 = blockIdx.x;
    float4 lvr[4], nvr[4];
    load_tile(p0, link, neigh, kk, sub, lvr, nvr);
    float pr_c = 1.f, tf_c = 0.f;
    if (sub == 0) {
        pr_c = __ldg(&probs[(size_t)p0 * K_NB + kk]);
        tf_c = g_tself[p0];
    }
    float2 ts_c[2] = {{0.f, 0.f}, {0.f, 0.f}};
    ts_load(p0, wn, lane, ts_c);
    __syncthreads();               // gwls/gwns visible

    for (int p = p0; p < N_NODES; p += G) {
        // ---- phase 1: stores + gate (register math only)
        store_h(ah + kk * AHP, sub, lvr);
        store_h(nvh + kk * AHP, sub, nvr);
        {
            const float4* gl = (const float4*)(gwls + sub * 16);
            const float4* gn = (const float4*)(gwns + sub * 16);
            float s0 = 0.f, s1 = 0.f;
            #pragma unroll
            for (int i = 0; i < 4; i++) {
                float4 a = lvr[i], b = gl[i];
                s0 = fmaf(a.x, b.x, fmaf(a.y, b.y,
                     fmaf(a.z, b.z, fmaf(a.w, b.w, s0))));
                float4 u = nvr[i], v = gn[i];
                s1 = fmaf(u.x, v.x, fmaf(u.y, v.y,
                     fmaf(u.z, v.z, fmaf(u.w, v.w, s1))));
            }
            float s = s0 + s1;
            s += __shfl_down_sync(0xffffffffu, s, 1, 8);
            s += __shfl_down_sync(0xffffffffu, s, 2, 8);
            s += __shfl_down_sync(0xffffffffu, s, 4, 8);
            if (sub == 0) {
                float g = sigmoid_tanh(tf_c + s);
                csh[kk] = __fdividef(g, pr_c) * (1.0f / (float)K_NB);
            }
        }
        __syncthreads();           // ah, nvh, csh visible

        // ---- phase 2: issue next-tile loads (latency hidden by GEMM+epi)
        int pn = p + G;
        float pr_n = 1.f, tf_n = 0.f;
        float2 ts_n[2] = {{0.f, 0.f}, {0.f, 0.f}};
        if (pn < N_NODES) {
            load_tile(pn, link, neigh, kk, sub, lvr, nvr);
            if (sub == 0) {
                pr_n = __ldg(&probs[(size_t)pn * K_NB + kk]);
                tf_n = g_tself[pn];
            }
            ts_load(pn, wn, lane, ts_n);
        }

        // ---- GEMM: warp covers rows lp(+8/16/24), cols wn*16..+16, K=128
        float acc0[2][4], acc1[2][4];
        #pragma unroll
        for (int ns = 0; ns < 2; ns++) {
            acc0[ns][0] = acc0[ns][1] = acc0[ns][2] = acc0[ns][3] = 0.0f;
            acc1[ns][0] = acc1[ns][1] = acc1[ns][2] = acc1[ns][3] = 0.0f;
        }
        {
            const unsigned* r0 = ah + lp * AHP;
            const unsigned* r1 = ah + (lp + 8) * AHP;
            const unsigned* r2 = ah + (lp + 16) * AHP;
            const unsigned* r3 = ah + (lp + 24) * AHP;
            #pragma unroll
            for (int ks = 0; ks < 8; ks++) {
                int d0 = ks * 4 + lq;
                unsigned a00 = r0[d0], a01 = r1[d0];
                unsigned a02 = r0[d0 + 32], a03 = r1[d0 + 32];
                unsigned a10 = r2[d0], a11 = r3[d0];
                unsigned a12 = r2[d0 + 32], a13 = r3[d0 + 32];
                uint4 B = Bf[ks];
                mma_f16(acc0[0][0], acc0[0][1], acc0[0][2], acc0[0][3],
                        a00, a01, a02, a03, B.x, B.y);
                mma_f16(acc0[1][0], acc0[1][1], acc0[1][2], acc0[1][3],
                        a00, a01, a02, a03, B.z, B.w);
                mma_f16(acc1[0][0], acc1[0][1], acc1[0][2], acc1[0][3],
                        a10, a11, a12, a13, B.x, B.y);
                mma_f16(acc1[1][0], acc1[1][1], acc1[1][2], acc1[1][3],
                        a10, a11, a12, a13, B.z, B.w);
            }
        }

        // ---- epilogue: reduce over 32 rows (in-warp), scale, relu, store
        {
            float cA = csh[lp];
            float cB = csh[lp + 8];
            float cC = csh[lp + 16];
            float cD = csh[lp + 24];
            const unsigned* n0 = nvh + lp * AHP;
            const unsigned* n1 = nvh + (lp + 8) * AHP;
            const unsigned* n2 = nvh + (lp + 16) * AHP;
            const unsigned* n3 = nvh + (lp + 24) * AHP;

            float ps[4];
            #pragma unroll
            for (int ns = 0; ns < 2; ns++) {
                int pos = ns * 32 + wn * 4 + lq;
                float2 v0 = __half22float2(*(const __half2*)&n0[pos]);
                float2 v1 = __half22float2(*(const __half2*)&n1[pos]);
                float2 v2 = __half22float2(*(const __half2*)&n2[pos]);
                float2 v3 = __half22float2(*(const __half2*)&n3[pos]);
                ps[ns * 2 + 0] = sigmoid_tanh(acc0[ns][0]) * v0.x * cA +
                                 sigmoid_tanh(acc0[ns][2]) * v1.x * cB +
                                 sigmoid_tanh(acc1[ns][0]) * v2.x * cC +
                                 sigmoid_tanh(acc1[ns][2]) * v3.x * cD;
                ps[ns * 2 + 1] = sigmoid_tanh(acc0[ns][1]) * v0.y * cA +
                                 sigmoid_tanh(acc0[ns][3]) * v1.y * cB +
                                 sigmoid_tanh(acc1[ns][1]) * v2.y * cC +
                                 sigmoid_tanh(acc1[ns][3]) * v3.y * cD;
            }
            #pragma unroll
            for (int o = 4; o <= 16; o <<= 1) {
                #pragma unroll
                for (int i = 0; i < 4; i++)
                    ps[i] += __shfl_xor_sync(0xffffffffu, ps[i], o);
            }
            if (lane < 4) {
                float* op = out + (size_t)p * D_DIM + wn * 16 + lane * 2;
                #pragma unroll
                for (int ns = 0; ns < 2; ns++) {
                    float2 r;
                    r.x = fmaxf(ts_c[ns].x * ps[ns * 2 + 0], 0.0f);
                    r.y = fmaxf(ts_c[ns].y * ps[ns * 2 + 1], 0.0f);
                    *(float2*)&op[ns * 8] = r;
                }
            }
        }
        __syncthreads();           // ah/nvh/csh reads done before next stores

        pr_c = pr_n;
        tf_c = tf_n;
        ts_c[0] = ts_n[0];
        ts_c[1] = ts_n[1];
    }
}

// ---------------- launch ----------------------------------------------------
extern "C" void kernel_launch(void* const* d_in, const int* in_sizes, int n_in,
                              void* d_out, int out_size) {
    const float* self_feats = (const float*)d_in[0];
    const float* self_vecs  = (const float*)d_in[1];
    const float* neigh      = (const float*)d_in[2];
    const float* link       = (const float*)d_in[3];
    const float* probs      = (const float*)d_in[4];
    const float* gws        = (const float*)d_in[5];
    const float* gwn        = (const float*)d_in[6];
    const float* gwl        = (const float*)d_in[7];
    const float* Ws         = (const float*)d_in[8];
    const float* Wl         = (const float*)d_in[9];
    float* out = (float*)d_out;

    const int smem_tsf  = (D_DIM * D_DIM + TSF_NODES * D_DIM) * sizeof(float); // 72 KB
    const int smem_main = (2 * 32 * AHP + 32 + 2 * D_DIM) * sizeof(float);     // ~19 KB

    cudaFuncSetAttribute(k_tsf,  cudaFuncAttributeMaxDynamicSharedMemorySize, smem_tsf);
    cudaFuncSetAttribute(k_main, cudaFuncAttributeMaxDynamicSharedMemorySize, smem_main);

    k_tself<<<(N_NODES * 32 + 255) / 256, 256>>>(self_vecs, gws);
    k_tsf<<<N_NODES / TSF_NODES, 256, smem_tsf>>>(self_feats, Ws);
    k_main<<<GRID, 256, smem_main>>>(neigh, link, probs, gwn, gwl, Wl, out);
}